// round 8
// baseline (speedup 1.0000x reference)
#include <cuda_runtime.h>
#include <cstdint>
#include <cstddef>

// Problem shape (fixed by setup_inputs)
#define B_     8
#define S_     4096
#define D_     1024
#define HALF   (S_ / 2)          // 2048 rows per scan block
#define CHUNK  128               // rows per pipeline stage
#define NCH    (HALF / CHUNK)    // 16 chunks per half
#define NBUF   3                 // pipeline depth
#define NCHAIN 256               // (batch, 32-lane d-tile) chains
#define NBLK   (NCHAIN * 2)      // 512 one-warp blocks
#define TPREP  256               // prep kernel threads
#define SPAN   (S_ / TPREP)      // 16 rows per prep thread

// Static device scratch (allowed; no dynamic allocation)
__device__ float4        g_tbl[B_][S_];      // (m, n, w, 0) per timestep
__device__ int           g_fr[B_];           // first reset index >= HALF (else S_)
__device__ volatile int  g_sflag[NCHAIN];    // half-0 final-S published
__device__ float         g_sval[NCHAIN][32];

__device__ __forceinline__ unsigned smem_u32(const void* p) {
    return (unsigned)__cvta_generic_to_shared(p);
}
__device__ __forceinline__ void cp16(unsigned dst, const void* src) {
    asm volatile("cp.async.cg.shared.global [%0], [%1], 16;\n" :: "r"(dst), "l"(src));
}
__device__ __forceinline__ void cp_commit() {
    asm volatile("cp.async.commit_group;\n");
}
template <int N>
__device__ __forceinline__ void cp_wait_n() {
    asm volatile("cp.async.wait_group %0;\n" :: "n"(N) : "memory");
}

// ---------------------------------------------------------------------------
// Prep kernel: one block per batch. Detects id dtype, builds exact
// position-in-group for all S timesteps (span scan), writes the per-timestep
// affine table (m, n, w) to global, publishes first reset >= HALF, and clears
// the cross-block handoff flags for this launch/replay.
// ---------------------------------------------------------------------------
__global__ void __launch_bounds__(TPREP)
prep_kernel(const int* __restrict__ idw)     // raw 32-bit word view of ids
{
    __shared__ unsigned short pos[S_];
    __shared__ unsigned short spanEnd[TPREP];
    __shared__ unsigned short spanCarry[TPREP];
    __shared__ unsigned char  spanFR[TPREP];
    __shared__ int modeAcc, frAcc;

    const int b   = blockIdx.x;
    const int tid = threadIdx.x;
    const int l   = tid & 31;

    if (tid == 0) { modeAcc = 0; frAcc = S_; }
    if (tid < 32) g_sflag[b * 32 + tid] = 0;   // clear handoff flags (8x32=256)
    __syncthreads();

    // dtype detect on globally-safe window: words [0,4096) are in-bounds under
    // both interpretations; odd words are int64 hi-halves (all zero) iff int64.
    {
        int acc = 0;
        #pragma unroll
        for (int k = 0; k < 8; k++)
            acc |= __ldg(&idw[2 * (tid * 8 + k) + 1]);
        #pragma unroll
        for (int o = 16; o; o >>= 1) acc |= __shfl_xor_sync(~0u, acc, o);
        if (l == 0) atomicOr(&modeAcc, acc);
    }
    __syncthreads();
    const bool mode64 = (modeAcc == 0);

    // pass A: each thread scans SPAN consecutive timesteps
    {
        const int base = tid * SPAN;
        int p = 0, fr = SPAN;
        #pragma unroll
        for (int j = 0; j < SPAN; j++) {
            int f;
            if (mode64) {
                int2 v = __ldg(((const int2*)idw) + (size_t)b * S_ + base + j);
                f = (v.x == 1) & (v.y == 0);
            } else {
                f = (__ldg(idw + (size_t)b * S_ + base + j) == 1);
            }
            p = f ? 1 : p + 1;
            if (f && fr == SPAN) fr = j;
            pos[base + j] = (unsigned short)p;
        }
        spanEnd[tid] = (unsigned short)p;
        spanFR[tid]  = (unsigned char)fr;
    }
    __syncthreads();

    // span scan (warp 0): carry = run length entering each span
    if (tid < 32) {
        int a = 0, bb = 1;
        #pragma unroll
        for (int k = 0; k < 8; k++) {
            int s  = tid * 8 + k;
            int hr = (spanFR[s] < SPAN);
            int e  = spanEnd[s];
            if (hr) { a = e; bb = 0; } else { a += SPAN; }
        }
        #pragma unroll
        for (int o = 1; o < 32; o <<= 1) {
            int pa = __shfl_up_sync(~0u, a,  o);
            int pb = __shfl_up_sync(~0u, bb, o);
            if (tid >= o) { a = a + bb * pa; bb = bb * pb; }
        }
        int ex = __shfl_up_sync(~0u, a, 1);
        if (tid == 0) ex = 0;
        int c = ex;
        #pragma unroll
        for (int k = 0; k < 8; k++) {
            int s = tid * 8 + k;
            spanCarry[s] = (unsigned short)c;
            int hr = (spanFR[s] < SPAN);
            c = hr ? (int)spanEnd[s] : c + SPAN;
        }
    }
    __syncthreads();

    // pass B: add incoming carry to pre-first-reset prefix of each span
    {
        const int base = tid * SPAN;
        int c  = spanCarry[tid];
        int fr = spanFR[tid];
        if (c) {
            #pragma unroll
            for (int j = 0; j < SPAN; j++)
                if (j < fr) pos[base + j] = (unsigned short)(pos[base + j] + c);
        }
    }
    __syncthreads();

    // write table + first reset >= HALF
    for (int i = tid; i < S_; i += TPREP) {
        int p = pos[i];
        float pf = (float)p;
        float m  = (p != 1) ? 1.0f : 0.0f;
        g_tbl[b][i] = make_float4(m, pf, __fdividef(1.0f, pf), 0.0f);
        if (p == 1 && i >= HALF) atomicMin(&frAcc, i);
    }
    __syncthreads();
    if (tid == 0) g_fr[b] = frAcc;
}

// ---------------------------------------------------------------------------
// Scan kernel: one WARP per (chain, S-half). No barriers, no cross-warp
// cooperation; per-thread cp.async commit groups give each warp a private
// 3-deep pipeline (wait_group 2 keeps 2 chunks permanently in flight).
// Half 1 runs with S=0 and applies the additive head fixup afterwards.
// ---------------------------------------------------------------------------
struct __align__(16) SmemS {
    float  xs[NBUF][CHUNK][32];   // 48 KB
    float4 ts[NBUF][CHUNK];       // 6 KB
};

__global__ void __launch_bounds__(32, 4)
scan_kernel(const float* __restrict__ emb,
            float* __restrict__ out)
{
    extern __shared__ char raw[];
    SmemS* sm = reinterpret_cast<SmemS*>(raw);

    const int l   = threadIdx.x;
    const int bid = blockIdx.x;
    const int h   = bid >> 8;          // S-half
    const int ch  = bid & 255;         // chain id
    const int b   = ch >> 5;
    const int d0  = (ch & 31) * 32;

    const float*  xg = emb + ((size_t)(b * S_ + h * HALF)) * D_ + d0;
    float*        og = out + ((size_t)(b * S_ + h * HALF)) * D_ + d0;
    const float4* tg = &g_tbl[b][h * HALF];

    // issue one chunk's loads (x tile + table slice) into its buffer
    auto issue = [&](int p) {
        const int buf = ((unsigned)p) % NBUF;
        const float* src = xg + (size_t)p * CHUNK * D_;
        #pragma unroll
        for (int k = 0; k < 32; k++) {
            int f = k * 32 + l, row = f >> 3, seg = f & 7;
            cp16(smem_u32(&sm->xs[buf][row][seg * 4]),
                 src + (size_t)row * D_ + seg * 4);
        }
        const float4* tsrc = tg + p * CHUNK;
        #pragma unroll
        for (int k = 0; k < 4; k++) {
            int r = k * 32 + l;
            cp16(smem_u32(&sm->ts[buf][r]), tsrc + r);
        }
    };

    #pragma unroll
    for (int p = 0; p < NBUF; p++) { issue(p); cp_commit(); }

    float S = 0.0f;
    for (int c = 0; c < NCH; ++c) {
        cp_wait_n<NBUF - 1>();     // chunk c complete; c+1, c+2 stay in flight
        __syncwarp();              // cross-thread visibility of deposits
        const int buf = ((unsigned)c) % NBUF;
        float* ob = og + (size_t)c * CHUNK * D_ + l;
        #pragma unroll 1
        for (int rr = 0; rr < CHUNK / 32; ++rr) {
            #pragma unroll
            for (int r = 0; r < 32; ++r) {
                const int row = rr * 32 + r;
                float4 t4 = sm->ts[buf][row];
                float  x  = sm->xs[buf][row][l];
                S = fmaf(S, t4.x, x * t4.y);
                ob[(size_t)row * D_] = S * t4.z;
            }
        }
        __syncwarp();              // all lanes done reading buf before refill
        if (c + NBUF < NCH) issue(c + NBUF);
        cp_commit();               // empty group near the tail keeps counts right
    }

    // ---- cross-half value handoff + head fixup ----
    if (h == 0) {
        g_sval[ch][l] = S;         // exact: half 0 starts at the true beginning
        __threadfence();
        if (l == 0) g_sflag[ch] = 1;
    } else {
        if (l == 0) {
            while (g_sflag[ch] == 0) __nanosleep(64);
        }
        __syncwarp();
        __threadfence();
        const float S_in = g_sval[ch][l];
        const int fr = g_fr[b];    // first reset >= HALF (S_ if none)
        for (int t = HALF; t < fr; ++t) {
            float wv = g_tbl[b][t].z;
            float* p = out + ((size_t)(b * S_ + t)) * D_ + d0 + l;
            *p += S_in * wv;
        }
    }
}

extern "C" void kernel_launch(void* const* d_in, const int* in_sizes, int n_in,
                              void* d_out, int out_size) {
    const float* emb = (const float*)d_in[0];
    const int*   idw = (const int*)d_in[1];
    float*       out = (float*)d_out;

    (void)in_sizes; (void)n_in; (void)out_size;

    cudaFuncSetAttribute(scan_kernel,
                         cudaFuncAttributeMaxDynamicSharedMemorySize,
                         (int)sizeof(SmemS));

    prep_kernel<<<B_, TPREP>>>(idw);                  // table + flags + clears
    scan_kernel<<<NBLK, 32, sizeof(SmemS)>>>(emb, out);
}